// round 6
// baseline (speedup 1.0000x reference)
#include <cuda_runtime.h>

// Problem dims (fixed by reference setup_inputs)
#define BB   2
#define SS   2048
#define DD   1024
#define NH   16
#define HW   64
#define MM   (BB * SS)   // 4096
#define BH   (BB * NH)   // 32

// ---------------- scratch (device globals; no allocation allowed) ----------
__device__ float g_q[MM * DD];
__device__ float g_k[MM * DD];
__device__ float g_v[MM * DD];
__device__ float g_sc[(size_t)BH * SS * SS];   // 512 MB scores scratch

// ---------------------------------------------------------------------------
// Kernel 1: C[m][n] = sum_k A[m][k] * Wt[n][k] + bias[n]   (GEMM-NT + bias)
// Tiles: BM=64, BN=64, BK=16. 256 threads, 4x4 per thread, stride-16 mapping.
// ---------------------------------------------------------------------------
__global__ __launch_bounds__(256) void gemm_nt_bias(
    const float* __restrict__ A, const float* __restrict__ Wt,
    const float* __restrict__ bias, float* __restrict__ C,
    int Kdim, int Ndim)
{
    __shared__ float As[16][65];
    __shared__ float Bs[16][65];

    const int t  = threadIdx.x;
    const int tx = t & 15;
    const int ty = t >> 4;
    const int m0 = blockIdx.y * 64;
    const int n0 = blockIdx.x * 64;

    const int lrow = t >> 2;          // 0..63
    const int lkv  = (t & 3) * 4;     // 0,4,8,12

    const float* Ap = A  + (size_t)(m0 + lrow) * Kdim + lkv;
    const float* Bp = Wt + (size_t)(n0 + lrow) * Kdim + lkv;

    float acc[4][4];
#pragma unroll
    for (int i = 0; i < 4; i++)
#pragma unroll
        for (int j = 0; j < 4; j++) acc[i][j] = 0.0f;

    for (int k0 = 0; k0 < Kdim; k0 += 16) {
        float4 av = *(const float4*)(Ap + k0);
        float4 bv = *(const float4*)(Bp + k0);
        __syncthreads();   // protect previous iteration's reads
        As[lkv + 0][lrow] = av.x; As[lkv + 1][lrow] = av.y;
        As[lkv + 2][lrow] = av.z; As[lkv + 3][lrow] = av.w;
        Bs[lkv + 0][lrow] = bv.x; Bs[lkv + 1][lrow] = bv.y;
        Bs[lkv + 2][lrow] = bv.z; Bs[lkv + 3][lrow] = bv.w;
        __syncthreads();
#pragma unroll
        for (int kk = 0; kk < 16; kk++) {
            float a[4], b[4];
#pragma unroll
            for (int i = 0; i < 4; i++) a[i] = As[kk][ty + i * 16];
#pragma unroll
            for (int j = 0; j < 4; j++) b[j] = Bs[kk][tx + j * 16];
#pragma unroll
            for (int i = 0; i < 4; i++)
#pragma unroll
                for (int j = 0; j < 4; j++)
                    acc[i][j] = fmaf(a[i], b[j], acc[i][j]);
        }
    }

#pragma unroll
    for (int j = 0; j < 4; j++) {
        float bb = bias[n0 + tx + j * 16];
#pragma unroll
        for (int i = 0; i < 4; i++)
            C[(size_t)(m0 + ty + i * 16) * Ndim + n0 + tx + j * 16] = acc[i][j] + bb;
    }
}

// ---------------------------------------------------------------------------
// Kernel 2: scores[bh][i][j] = 0.125 * sum_w q_h[i][w] * k_h[j][w]
// One 64x64 output tile per block; K = 64 (head width) fits entirely in smem.
// ---------------------------------------------------------------------------
__global__ __launch_bounds__(256) void qk_kernel()
{
    __shared__ float Qs[64][65];   // [w][i]
    __shared__ float Ks[64][65];   // [w][j]

    const int t  = threadIdx.x;
    const int tx = t & 15;
    const int ty = t >> 4;
    const int bh = blockIdx.z;
    const int b  = bh >> 4;
    const int h  = bh & 15;
    const int i0 = blockIdx.y * 64;
    const int j0 = blockIdx.x * 64;

    const float* qbase = g_q + (size_t)(b * SS) * DD + h * HW;
    const float* kbase = g_k + (size_t)(b * SS) * DD + h * HW;

#pragma unroll
    for (int r = 0; r < 4; r++) {
        int idx = r * 256 + t;
        int row = idx >> 4;
        int wv  = (idx & 15) * 4;
        float4 qv = *(const float4*)(qbase + (size_t)(i0 + row) * DD + wv);
        float4 kv = *(const float4*)(kbase + (size_t)(j0 + row) * DD + wv);
        Qs[wv + 0][row] = qv.x; Qs[wv + 1][row] = qv.y;
        Qs[wv + 2][row] = qv.z; Qs[wv + 3][row] = qv.w;
        Ks[wv + 0][row] = kv.x; Ks[wv + 1][row] = kv.y;
        Ks[wv + 2][row] = kv.z; Ks[wv + 3][row] = kv.w;
    }
    __syncthreads();

    float acc[4][4];
#pragma unroll
    for (int i = 0; i < 4; i++)
#pragma unroll
        for (int j = 0; j < 4; j++) acc[i][j] = 0.0f;

#pragma unroll 16
    for (int w = 0; w < 64; w++) {
        float a[4], b4[4];
#pragma unroll
        for (int i = 0; i < 4; i++) a[i]  = Qs[w][ty + i * 16];
#pragma unroll
        for (int j = 0; j < 4; j++) b4[j] = Ks[w][tx + j * 16];
#pragma unroll
        for (int i = 0; i < 4; i++)
#pragma unroll
            for (int j = 0; j < 4; j++)
                acc[i][j] = fmaf(a[i], b4[j], acc[i][j]);
    }

    float* out = g_sc + (size_t)bh * SS * SS;
#pragma unroll
    for (int i = 0; i < 4; i++)
#pragma unroll
        for (int j = 0; j < 4; j++)
            out[(size_t)(i0 + ty + i * 16) * SS + j0 + tx + j * 16] = acc[i][j] * 0.125f;
}

// ---------------------------------------------------------------------------
// Kernel 3: double softmax over each row of scores (length 2048).
// One block (256 thr) per row; whole row lives in registers (8/thread).
// softmax(softmax(z)): p = exp(z-m)/Z with m=max(z); then since max(p)=1/Z,
// out = exp(p - 1/Z) / sum(exp(p - 1/Z)).
// ---------------------------------------------------------------------------
__device__ __forceinline__ float warpRedMax(float x) {
#pragma unroll
    for (int o = 16; o > 0; o >>= 1) x = fmaxf(x, __shfl_xor_sync(0xffffffffu, x, o));
    return x;
}
__device__ __forceinline__ float warpRedSum(float x) {
#pragma unroll
    for (int o = 16; o > 0; o >>= 1) x += __shfl_xor_sync(0xffffffffu, x, o);
    return x;
}

__global__ __launch_bounds__(256) void softmax2_kernel()
{
    __shared__ float red[8];
    const int t = threadIdx.x;
    float* p = g_sc + (size_t)blockIdx.x * SS;

    float v[8];
#pragma unroll
    for (int j = 0; j < 8; j++) v[j] = p[t + j * 256];

    // row max
    float m = v[0];
#pragma unroll
    for (int j = 1; j < 8; j++) m = fmaxf(m, v[j]);
    m = warpRedMax(m);
    if ((t & 31) == 0) red[t >> 5] = m;
    __syncthreads();
    m = red[0];
#pragma unroll
    for (int i = 1; i < 8; i++) m = fmaxf(m, red[i]);

    // first softmax numerators + sum
    float e[8], z = 0.0f;
#pragma unroll
    for (int j = 0; j < 8; j++) { e[j] = __expf(v[j] - m); z += e[j]; }
    z = warpRedSum(z);
    __syncthreads();
    if ((t & 31) == 0) red[t >> 5] = z;
    __syncthreads();
    z = red[0] + red[1] + red[2] + red[3] + red[4] + red[5] + red[6] + red[7];
    float inv = 1.0f / z;       // == max of first-softmax output

    // second softmax
    float f[8], s2 = 0.0f;
#pragma unroll
    for (int j = 0; j < 8; j++) { f[j] = __expf(fmaf(e[j], inv, -inv)); s2 += f[j]; }
    s2 = warpRedSum(s2);
    __syncthreads();
    if ((t & 31) == 0) red[t >> 5] = s2;
    __syncthreads();
    s2 = red[0] + red[1] + red[2] + red[3] + red[4] + red[5] + red[6] + red[7];
    float is2 = 1.0f / s2;

#pragma unroll
    for (int j = 0; j < 8; j++) p[t + j * 256] = f[j] * is2;
}

// ---------------------------------------------------------------------------
// Kernel 4: out[b][i][h*64+w] = sum_j P[bh][i][j] * v_h[j][w]
// BM=64, BN=64(full head), BK=16. Streams the 512MB scores once.
// ---------------------------------------------------------------------------
__global__ __launch_bounds__(256) void pv_kernel(float* __restrict__ out)
{
    __shared__ float Ps[16][65];   // [j][i] transposed
    __shared__ float Vs[16][64];   // [j][w] natural

    const int t  = threadIdx.x;
    const int tx = t & 15;
    const int ty = t >> 4;
    const int bh = blockIdx.y;
    const int b  = bh >> 4;
    const int h  = bh & 15;
    const int m0 = blockIdx.x * 64;

    const int lrow = t >> 2;         // P tile row 0..63
    const int lkv  = (t & 3) * 4;    // P tile k-offset
    const int vrow = t >> 4;         // V tile row 0..15
    const int wv   = (t & 15) * 4;   // V tile w-offset

    const float* Pp = g_sc + (size_t)bh * SS * SS + (size_t)(m0 + lrow) * SS + lkv;
    const float* Vp = g_v + (size_t)(b * SS + vrow) * DD + h * HW + wv;

    float acc[4][4];
#pragma unroll
    for (int i = 0; i < 4; i++)
#pragma unroll
        for (int j = 0; j < 4; j++) acc[i][j] = 0.0f;

    for (int k0 = 0; k0 < SS; k0 += 16) {
        float4 pv4 = *(const float4*)(Pp + k0);
        float4 vv  = *(const float4*)(Vp + (size_t)k0 * DD);
        __syncthreads();
        Ps[lkv + 0][lrow] = pv4.x; Ps[lkv + 1][lrow] = pv4.y;
        Ps[lkv + 2][lrow] = pv4.z; Ps[lkv + 3][lrow] = pv4.w;
        *(float4*)&Vs[vrow][wv] = vv;
        __syncthreads();
#pragma unroll
        for (int kk = 0; kk < 16; kk++) {
            float a[4], b4[4];
#pragma unroll
            for (int i = 0; i < 4; i++) a[i]  = Ps[kk][ty + i * 16];
#pragma unroll
            for (int j = 0; j < 4; j++) b4[j] = Vs[kk][tx + j * 16];
#pragma unroll
            for (int i = 0; i < 4; i++)
#pragma unroll
                for (int j = 0; j < 4; j++)
                    acc[i][j] = fmaf(a[i], b4[j], acc[i][j]);
        }
    }

#pragma unroll
    for (int i = 0; i < 4; i++)
#pragma unroll
        for (int j = 0; j < 4; j++)
            out[(size_t)(b * SS + m0 + ty + i * 16) * DD + h * HW + tx + j * 16] = acc[i][j];
}

// ---------------------------------------------------------------------------
extern "C" void kernel_launch(void* const* d_in, const int* in_sizes, int n_in,
                              void* d_out, int out_size)
{
    const float* x  = (const float*)d_in[0];
    const float* Wq = (const float*)d_in[1];
    const float* bq = (const float*)d_in[2];
    const float* Wk = (const float*)d_in[3];
    const float* bk = (const float*)d_in[4];
    const float* Wv = (const float*)d_in[5];
    const float* bv = (const float*)d_in[6];
    float* out = (float*)d_out;

    float *q, *k, *v;
    cudaGetSymbolAddress((void**)&q, g_q);
    cudaGetSymbolAddress((void**)&k, g_k);
    cudaGetSymbolAddress((void**)&v, g_v);

    // 1) QKV projections: M=4096, N=1024, K=1024, NT layout
    dim3 gGrid(DD / 64, MM / 64);
    gemm_nt_bias<<<gGrid, 256>>>(x, Wq, bq, q, DD, DD);
    gemm_nt_bias<<<gGrid, 256>>>(x, Wk, bk, k, DD, DD);
    gemm_nt_bias<<<gGrid, 256>>>(x, Wv, bv, v, DD, DD);

    // 2) scores = scale * q @ k^T per (b,h)
    dim3 qkGrid(SS / 64, SS / 64, BH);
    qk_kernel<<<qkGrid, 256>>>();

    // 3) double softmax over rows
    softmax2_kernel<<<BH * SS, 256>>>();

    // 4) out = scores @ v per (b,h), written in (B,S,D) interleaved-head layout
    dim3 pvGrid(SS / 64, BH);
    pv_kernel<<<pvGrid, 256>>>(out);
}

// round 8
// speedup vs baseline: 1.3362x; 1.3362x over previous
#include <cuda_runtime.h>
#include <cstdint>

// Problem dims (fixed by reference setup_inputs)
#define BB   2
#define SS   2048
#define DD   1024
#define NH   16
#define HW   64
#define MM   (BB * SS)   // 4096
#define BH   (BB * NH)   // 32

// ---------------- scratch (device globals; no allocation allowed) ----------
__device__ float g_q[MM * DD];
__device__ float g_k[MM * DD];
__device__ float g_v[MM * DD];
__device__ float g_sc[(size_t)BH * SS * SS];   // 512 MB scores scratch

// ---------------------------------------------------------------------------
// tf32 mma helpers (m16n8k8, row.col)
// ---------------------------------------------------------------------------
__device__ __forceinline__ uint32_t f2tf(float f) {
    uint32_t u;
    asm("cvt.rna.tf32.f32 %0, %1;" : "=r"(u) : "f"(f));
    return u;
}
__device__ __forceinline__ void mma8(float c[4], const uint32_t a[4], const uint32_t b[2]) {
    asm volatile(
        "mma.sync.aligned.m16n8k8.row.col.f32.tf32.tf32.f32 "
        "{%0,%1,%2,%3},{%4,%5,%6,%7},{%8,%9},{%0,%1,%2,%3};"
        : "+f"(c[0]), "+f"(c[1]), "+f"(c[2]), "+f"(c[3])
        : "r"(a[0]), "r"(a[1]), "r"(a[2]), "r"(a[3]), "r"(b[0]), "r"(b[1]));
}

// ---------------------------------------------------------------------------
// Kernel 1: projections. C[m][n] = sum_k A[m][k]*Wt[n][k] + bias[n]
// M=4096 N=1024 K=1024, NT. BM=BN=128, BK=16, 8 warps (2x4), warp tile 64x32.
// SPLIT=true -> 3xTF32 (near-fp32 accuracy) for the V projection.
// ---------------------------------------------------------------------------
template<bool SPLIT>
__global__ __launch_bounds__(256) void proj_kernel(
    const float* __restrict__ A, const float* __restrict__ Wt,
    const float* __restrict__ bias, float* __restrict__ C)
{
    __shared__ float As[128][20];   // [m][k], pad 20 -> conflict-free frag reads
    __shared__ float Bs[128][20];   // [n][k]

    const int t    = threadIdx.x;
    const int lane = t & 31;
    const int warp = t >> 5;
    const int wm   = warp >> 2;     // 0..1  (64 rows each)
    const int wn   = warp & 3;      // 0..3  (32 cols each)
    const int g    = lane >> 2;     // group id
    const int tg   = lane & 3;      // thread in group
    const int m0   = blockIdx.y * 128;
    const int n0   = blockIdx.x * 128;

    const int lrow = t >> 2;        // 0..63
    const int lkq  = (t & 3) << 2;  // 0,4,8,12

    float acc[4][4][4];
#pragma unroll
    for (int i = 0; i < 4; i++)
#pragma unroll
        for (int j = 0; j < 4; j++)
#pragma unroll
            for (int q = 0; q < 4; q++) acc[i][j][q] = 0.0f;

    for (int k0 = 0; k0 < DD; k0 += 16) {
        float4 ar[2], br[2];
#pragma unroll
        for (int r = 0; r < 2; r++) {
            int row = r * 64 + lrow;
            ar[r] = *(const float4*)(A  + (size_t)(m0 + row) * DD + k0 + lkq);
            br[r] = *(const float4*)(Wt + (size_t)(n0 + row) * DD + k0 + lkq);
        }
        __syncthreads();
#pragma unroll
        for (int r = 0; r < 2; r++) {
            int row = r * 64 + lrow;
            As[row][lkq + 0] = ar[r].x; As[row][lkq + 1] = ar[r].y;
            As[row][lkq + 2] = ar[r].z; As[row][lkq + 3] = ar[r].w;
            Bs[row][lkq + 0] = br[r].x; Bs[row][lkq + 1] = br[r].y;
            Bs[row][lkq + 2] = br[r].z; Bs[row][lkq + 3] = br[r].w;
        }
        __syncthreads();

#pragma unroll
        for (int ks = 0; ks < 16; ks += 8) {
            uint32_t ah[4][4], al[4][4];
#pragma unroll
            for (int mt = 0; mt < 4; mt++) {
                int mr = wm * 64 + mt * 16 + g;
#pragma unroll
                for (int q = 0; q < 4; q++) {
                    int rr = mr + (q & 1) * 8;
                    int kk = ks + tg + (q >> 1) * 4;
                    float fv = As[rr][kk];
                    ah[mt][q] = f2tf(fv);
                    if (SPLIT) al[mt][q] = f2tf(fv - __uint_as_float(ah[mt][q]));
                }
            }
            uint32_t bh[4][2], bl[4][2];
#pragma unroll
            for (int nt = 0; nt < 4; nt++) {
                int nc = wn * 32 + nt * 8 + g;
#pragma unroll
                for (int q = 0; q < 2; q++) {
                    float fv = Bs[nc][ks + tg + q * 4];
                    bh[nt][q] = f2tf(fv);
                    if (SPLIT) bl[nt][q] = f2tf(fv - __uint_as_float(bh[nt][q]));
                }
            }
#pragma unroll
            for (int mt = 0; mt < 4; mt++)
#pragma unroll
                for (int nt = 0; nt < 4; nt++) {
                    mma8(acc[mt][nt], ah[mt], bh[nt]);
                    if (SPLIT) {
                        mma8(acc[mt][nt], ah[mt], bl[nt]);
                        mma8(acc[mt][nt], al[mt], bh[nt]);
                    }
                }
        }
    }

#pragma unroll
    for (int mt = 0; mt < 4; mt++)
#pragma unroll
        for (int nt = 0; nt < 4; nt++) {
            int row = m0 + wm * 64 + mt * 16 + g;
            int col = n0 + wn * 32 + nt * 8 + tg * 2;
            float b0 = bias[col], b1 = bias[col + 1];
            C[(size_t)row * DD + col]           = acc[mt][nt][0] + b0;
            C[(size_t)row * DD + col + 1]       = acc[mt][nt][1] + b1;
            C[(size_t)(row + 8) * DD + col]     = acc[mt][nt][2] + b0;
            C[(size_t)(row + 8) * DD + col + 1] = acc[mt][nt][3] + b1;
        }
}

// ---------------------------------------------------------------------------
// Kernel 2: scores[bh][i][j] = 0.125 * q_h[i]·k_h[j]. 1xTF32 (error washed
// out by the double softmax). BM=BN=128, BK=32 (2 iters over head width 64).
// ---------------------------------------------------------------------------
__global__ __launch_bounds__(256) void qk_kernel()
{
    __shared__ float Qs[128][36];
    __shared__ float Ks[128][36];

    const int t    = threadIdx.x;
    const int lane = t & 31;
    const int warp = t >> 5;
    const int wm   = warp >> 2;
    const int wn   = warp & 3;
    const int g    = lane >> 2;
    const int tg   = lane & 3;
    const int bh   = blockIdx.z;
    const int b    = bh >> 4;
    const int h    = bh & 15;
    const int i0   = blockIdx.y * 128;
    const int j0   = blockIdx.x * 128;

    const float* qb = g_q + (size_t)(b * SS) * DD + h * HW;
    const float* kb = g_k + (size_t)(b * SS) * DD + h * HW;

    float acc[4][4][4];
#pragma unroll
    for (int i = 0; i < 4; i++)
#pragma unroll
        for (int j = 0; j < 4; j++)
#pragma unroll
            for (int q = 0; q < 4; q++) acc[i][j][q] = 0.0f;

    const int lrow8 = t >> 3;        // 0..31
    const int lkq8  = (t & 7) * 4;   // 0..28

    for (int k0 = 0; k0 < HW; k0 += 32) {
        float4 qr[4], kr[4];
#pragma unroll
        for (int r = 0; r < 4; r++) {
            int row = r * 32 + lrow8;
            qr[r] = *(const float4*)(qb + (size_t)(i0 + row) * DD + k0 + lkq8);
            kr[r] = *(const float4*)(kb + (size_t)(j0 + row) * DD + k0 + lkq8);
        }
        __syncthreads();
#pragma unroll
        for (int r = 0; r < 4; r++) {
            int row = r * 32 + lrow8;
            Qs[row][lkq8 + 0] = qr[r].x; Qs[row][lkq8 + 1] = qr[r].y;
            Qs[row][lkq8 + 2] = qr[r].z; Qs[row][lkq8 + 3] = qr[r].w;
            Ks[row][lkq8 + 0] = kr[r].x; Ks[row][lkq8 + 1] = kr[r].y;
            Ks[row][lkq8 + 2] = kr[r].z; Ks[row][lkq8 + 3] = kr[r].w;
        }
        __syncthreads();

#pragma unroll
        for (int ks = 0; ks < 32; ks += 8) {
            uint32_t af[4][4];
#pragma unroll
            for (int mt = 0; mt < 4; mt++) {
                int mr = wm * 64 + mt * 16 + g;
#pragma unroll
                for (int q = 0; q < 4; q++)
                    af[mt][q] = f2tf(Qs[mr + (q & 1) * 8][ks + tg + (q >> 1) * 4]);
            }
            uint32_t bf[4][2];
#pragma unroll
            for (int nt = 0; nt < 4; nt++) {
                int nc = wn * 32 + nt * 8 + g;
#pragma unroll
                for (int q = 0; q < 2; q++)
                    bf[nt][q] = f2tf(Ks[nc][ks + tg + q * 4]);
            }
#pragma unroll
            for (int mt = 0; mt < 4; mt++)
#pragma unroll
                for (int nt = 0; nt < 4; nt++)
                    mma8(acc[mt][nt], af[mt], bf[nt]);
        }
    }

    float* out = g_sc + (size_t)bh * SS * SS;
#pragma unroll
    for (int mt = 0; mt < 4; mt++)
#pragma unroll
        for (int nt = 0; nt < 4; nt++) {
            int row = i0 + wm * 64 + mt * 16 + g;
            int col = j0 + wn * 32 + nt * 8 + tg * 2;
            out[(size_t)row * SS + col]           = acc[mt][nt][0] * 0.125f;
            out[(size_t)row * SS + col + 1]       = acc[mt][nt][1] * 0.125f;
            out[(size_t)(row + 8) * SS + col]     = acc[mt][nt][2] * 0.125f;
            out[(size_t)(row + 8) * SS + col + 1] = acc[mt][nt][3] * 0.125f;
        }
}

// ---------------------------------------------------------------------------
// Kernel 3: double softmax over each 2048-length row (unchanged, fp32).
// ---------------------------------------------------------------------------
__device__ __forceinline__ float warpRedMax(float x) {
#pragma unroll
    for (int o = 16; o > 0; o >>= 1) x = fmaxf(x, __shfl_xor_sync(0xffffffffu, x, o));
    return x;
}
__device__ __forceinline__ float warpRedSum(float x) {
#pragma unroll
    for (int o = 16; o > 0; o >>= 1) x += __shfl_xor_sync(0xffffffffu, x, o);
    return x;
}

__global__ __launch_bounds__(256) void softmax2_kernel()
{
    __shared__ float red[8];
    const int t = threadIdx.x;
    float* p = g_sc + (size_t)blockIdx.x * SS;

    float v[8];
#pragma unroll
    for (int j = 0; j < 8; j++) v[j] = p[t + j * 256];

    float m = v[0];
#pragma unroll
    for (int j = 1; j < 8; j++) m = fmaxf(m, v[j]);
    m = warpRedMax(m);
    if ((t & 31) == 0) red[t >> 5] = m;
    __syncthreads();
    m = red[0];
#pragma unroll
    for (int i = 1; i < 8; i++) m = fmaxf(m, red[i]);

    float e[8], z = 0.0f;
#pragma unroll
    for (int j = 0; j < 8; j++) { e[j] = __expf(v[j] - m); z += e[j]; }
    z = warpRedSum(z);
    __syncthreads();
    if ((t & 31) == 0) red[t >> 5] = z;
    __syncthreads();
    z = red[0] + red[1] + red[2] + red[3] + red[4] + red[5] + red[6] + red[7];
    float inv = 1.0f / z;   // == max of first-softmax output

    float f[8], s2 = 0.0f;
#pragma unroll
    for (int j = 0; j < 8; j++) { f[j] = __expf(fmaf(e[j], inv, -inv)); s2 += f[j]; }
    s2 = warpRedSum(s2);
    __syncthreads();
    if ((t & 31) == 0) red[t >> 5] = s2;
    __syncthreads();
    s2 = red[0] + red[1] + red[2] + red[3] + red[4] + red[5] + red[6] + red[7];
    float is2 = 1.0f / s2;

#pragma unroll
    for (int j = 0; j < 8; j++) p[t + j * 256] = f[j] * is2;
}

// ---------------------------------------------------------------------------
// Kernel 4: out = P @ V per (b,h), 3xTF32 split (V path needs precision).
// BM=128, BN=64(full head), BK=32. 8 warps (4x2), warp tile 32x32.
// ---------------------------------------------------------------------------
__global__ __launch_bounds__(256) void pv_kernel(float* __restrict__ out)
{
    __shared__ float Ps[128][36];   // [i][j]
    __shared__ float Vs[32][72];    // [j][w], pad 72 -> conflict-free b-frag

    const int t    = threadIdx.x;
    const int lane = t & 31;
    const int warp = t >> 5;
    const int wm   = warp >> 1;     // 0..3  (32 rows each)
    const int wn   = warp & 1;      // 0..1  (32 cols each)
    const int g    = lane >> 2;
    const int tg   = lane & 3;
    const int bh   = blockIdx.y;
    const int b    = bh >> 4;
    const int h    = bh & 15;
    const int m0   = blockIdx.x * 128;

    const float* scp = g_sc + (size_t)bh * SS * SS;
    const float* vb  = g_v + (size_t)(b * SS) * DD + h * HW;

    float acc[2][4][4];
#pragma unroll
    for (int i = 0; i < 2; i++)
#pragma unroll
        for (int j = 0; j < 4; j++)
#pragma unroll
            for (int q = 0; q < 4; q++) acc[i][j][q] = 0.0f;

    const int prow = t >> 3;          // 0..31
    const int pkq  = (t & 7) * 4;
    const int vrow = t >> 4;          // 0..15
    const int vwq  = (t & 15) * 4;

    for (int k0 = 0; k0 < SS; k0 += 32) {
        float4 pr[4], vr[2];
#pragma unroll
        for (int r = 0; r < 4; r++)
            pr[r] = *(const float4*)(scp + (size_t)(m0 + r * 32 + prow) * SS + k0 + pkq);
#pragma unroll
        for (int r = 0; r < 2; r++)
            vr[r] = *(const float4*)(vb + (size_t)(k0 + r * 16 + vrow) * DD + vwq);
        __syncthreads();
#pragma unroll
        for (int r = 0; r < 4; r++) {
            int row = r * 32 + prow;
            Ps[row][pkq + 0] = pr[r].x; Ps[row][pkq + 1] = pr[r].y;
            Ps[row][pkq + 2] = pr[r].z; Ps[row][pkq + 3] = pr[r].w;
        }
#pragma unroll
        for (int r = 0; r < 2; r++) {
            int row = r * 16 + vrow;
            Vs[row][vwq + 0] = vr[r].x; Vs[row][vwq + 1] = vr[r].y;
            Vs[row][vwq + 2] = vr[r].z; Vs[row][vwq + 3] = vr[r].w;
        }
        __syncthreads();

#pragma unroll
        for (int ks = 0; ks < 32; ks += 8) {
            uint32_t ah[2][4], al[2][4];
#pragma unroll
            for (int mt = 0; mt < 2; mt++) {
                int mr = wm * 32 + mt * 16 + g;
#pragma unroll
                for (int q = 0; q < 4; q++) {
                    float fv = Ps[mr + (q & 1) * 8][ks + tg + (q >> 1) * 4];
                    ah[mt][q] = f2tf(fv);
                    al[mt][q] = f2tf(fv - __uint_as_float(ah[mt][q]));
                }
            }
            uint32_t bhv[4][2], blv[4][2];
#pragma unroll
            for (int nt = 0; nt < 4; nt++) {
                int nc = wn * 32 + nt * 8 + g;
#pragma unroll
                for (int q = 0; q < 2; q++) {
                    float fv = Vs[ks + tg + q * 4][nc];
                    bhv[nt][q] = f2tf(fv);
                    blv[nt][q] = f2tf(fv - __uint_as_float(bhv[nt][q]));
                }
            }
#pragma unroll
            for (int mt = 0; mt < 2; mt++)
#pragma unroll
                for (int nt = 0; nt < 4; nt++) {
                    mma8(acc[mt][nt], ah[mt], bhv[nt]);
                    mma8(acc[mt][nt], ah[mt], blv[nt]);
                    mma8(acc[mt][nt], al[mt], bhv[nt]);
                }
        }
    }

#pragma unroll
    for (int mt = 0; mt < 2; mt++)
#pragma unroll
        for (int nt = 0; nt < 4; nt++) {
            int row = b * SS + m0 + wm * 32 + mt * 16 + g;
            int col = h * HW + wn * 32 + nt * 8 + tg * 2;
            out[(size_t)row * DD + col]           = acc[mt][nt][0];
            out[(size_t)row * DD + col + 1]       = acc[mt][nt][1];
            out[(size_t)(row + 8) * DD + col]     = acc[mt][nt][2];
            out[(size_t)(row + 8) * DD + col + 1] = acc[mt][nt][3];
        }
}

// ---------------------------------------------------------------------------
extern "C" void kernel_launch(void* const* d_in, const int* in_sizes, int n_in,
                              void* d_out, int out_size)
{
    const float* x  = (const float*)d_in[0];
    const float* Wq = (const float*)d_in[1];
    const float* bq = (const float*)d_in[2];
    const float* Wk = (const float*)d_in[3];
    const float* bk = (const float*)d_in[4];
    const float* Wv = (const float*)d_in[5];
    const float* bv = (const float*)d_in[6];
    float* out = (float*)d_out;

    float *q, *k, *v;
    cudaGetSymbolAddress((void**)&q, g_q);
    cudaGetSymbolAddress((void**)&k, g_k);
    cudaGetSymbolAddress((void**)&v, g_v);

    // 1) QKV projections (tf32 mma; V with 3xTF32 split for accuracy)
    dim3 pGrid(DD / 128, MM / 128);
    proj_kernel<false><<<pGrid, 256>>>(x, Wq, bq, q);
    proj_kernel<false><<<pGrid, 256>>>(x, Wk, bk, k);
    proj_kernel<true ><<<pGrid, 256>>>(x, Wv, bv, v);

    // 2) scores = 0.125 * q @ k^T per (b,h)   (1xTF32)
    dim3 qkGrid(SS / 128, SS / 128, BH);
    qk_kernel<<<qkGrid, 256>>>();

    // 3) double softmax over rows
    softmax2_kernel<<<BH * SS, 256>>>();

    // 4) out = P @ V per (b,h)   (3xTF32)
    dim3 pvGrid(SS / 128, BH);
    pv_kernel<<<pvGrid, 256>>>(out);
}